// round 2
// baseline (speedup 1.0000x reference)
#include <cuda_runtime.h>
#include <cuda_bf16.h>
#include <math.h>

#define S_LEN 2048
#define NHEAD 71
#define HDIM  64
#define H_DIM (NHEAD * HDIM)          /* 4544 */
#define QKV_N ((NHEAD + 2) * HDIM)    /* 4672 */

/* ---- scratch (no allocs allowed: __device__ globals) ---- */
__device__ float g_qkv[(size_t)S_LEN * QKV_N];           /* 38 MB */
__device__ float g_q[(size_t)NHEAD * S_LEN * HDIM];      /* 37 MB, head-major */
__device__ float g_k[(size_t)S_LEN * HDIM];
__device__ float g_v[(size_t)S_LEN * HDIM];
__device__ float g_attn[(size_t)S_LEN * H_DIM];          /* 37 MB */

/* =====================================================================
 * SGEMM: C[M,N] = A[M,K] * B[K,N]  (row-major), BM=128 BN=64 BK=16,
 * 256 threads, 8x4 micro-tile per thread. M%128==0, N%64==0, K%16==0.
 * ===================================================================== */
__global__ void sgemm_kernel(const float* __restrict__ A,
                             const float* __restrict__ B,
                             float* __restrict__ C,
                             int M, int N, int K) {
    __shared__ float As[16][132];   /* transposed A tile, padded */
    __shared__ float Bs[16][64];

    const int tid    = threadIdx.x;
    const int rowBlk = blockIdx.y * 128;
    const int colBlk = blockIdx.x * 64;
    const int r0 = (tid >> 4) * 8;      /* 0..120 */
    const int c0 = (tid & 15) * 4;      /* 0..60  */
    const int aRow = tid >> 2;          /* 0..63  */
    const int aCol = (tid & 3) * 4;     /* 0,4,8,12 */
    const int bRow = tid >> 4;          /* 0..15  */
    const int bCol = (tid & 15) * 4;

    const float* Ap = A + (size_t)(rowBlk + aRow) * K + aCol;
    const float* Bp = B + (size_t)bRow * N + colBlk + bCol;

    float acc[8][4];
#pragma unroll
    for (int i = 0; i < 8; i++)
#pragma unroll
        for (int j = 0; j < 4; j++) acc[i][j] = 0.0f;

    for (int k0 = 0; k0 < K; k0 += 16) {
        float4 a0 = *(const float4*)Ap;
        float4 a1 = *(const float4*)(Ap + (size_t)64 * K);
        float4 b0 = *(const float4*)Bp;

        As[aCol + 0][aRow] = a0.x;
        As[aCol + 1][aRow] = a0.y;
        As[aCol + 2][aRow] = a0.z;
        As[aCol + 3][aRow] = a0.w;
        As[aCol + 0][aRow + 64] = a1.x;
        As[aCol + 1][aRow + 64] = a1.y;
        As[aCol + 2][aRow + 64] = a1.z;
        As[aCol + 3][aRow + 64] = a1.w;
        *(float4*)&Bs[bRow][bCol] = b0;
        __syncthreads();

#pragma unroll
        for (int kk = 0; kk < 16; kk++) {
            float4 av0 = *(const float4*)&As[kk][r0];
            float4 av1 = *(const float4*)&As[kk][r0 + 4];
            float4 bv  = *(const float4*)&Bs[kk][c0];
            float a[8] = {av0.x, av0.y, av0.z, av0.w, av1.x, av1.y, av1.z, av1.w};
            float b[4] = {bv.x, bv.y, bv.z, bv.w};
#pragma unroll
            for (int i = 0; i < 8; i++)
#pragma unroll
                for (int j = 0; j < 4; j++) acc[i][j] = fmaf(a[i], b[j], acc[i][j]);
        }
        __syncthreads();
        Ap += 16;
        Bp += (size_t)16 * N;
    }

#pragma unroll
    for (int i = 0; i < 8; i++) {
        float4 o = make_float4(acc[i][0], acc[i][1], acc[i][2], acc[i][3]);
        *(float4*)&C[(size_t)(rowBlk + r0 + i) * N + colBlk + c0] = o;
    }
}

/* =====================================================================
 * RoPE + split: qkv[2048, 4672] -> q[h][s][d] (roped), k[s][d] (roped),
 * v[s][d] (raw). Freqs: angle = s * 10000^(-(d%32)/32).
 * ===================================================================== */
__global__ void rope_split_kernel(const float* __restrict__ qkv,
                                  float* __restrict__ q,
                                  float* __restrict__ k,
                                  float* __restrict__ v) {
    const int s = blockIdx.x;
    const float* row = qkv + (size_t)s * QKV_N;
    const float fs = (float)s;
    const float L2C = 13.28771237954945f / 32.0f;   /* log2(10000)/32 */

    for (int col = threadIdx.x; col < QKV_N; col += blockDim.x) {
        const int h = col >> 6;
        const int d = col & 63;
        float val = row[col];
        if (h < NHEAD + 1) {
            const int jj = d & 31;
            float inv = exp2f(-(float)jj * L2C);
            float ang = fs * inv;
            float sn, cs;
            sincosf(ang, &sn, &cs);
            float other = (d < 32) ? -row[h * 64 + d + 32] : row[h * 64 + d - 32];
            float o = val * cs + other * sn;
            if (h < NHEAD)
                q[((size_t)h * S_LEN + s) * HDIM + d] = o;
            else
                k[(size_t)s * HDIM + d] = o;
        } else {
            v[(size_t)s * HDIM + d] = val;
        }
    }
}

/* =====================================================================
 * Flash-style causal attention. Block = (q-tile of 64 rows, head).
 * Online softmax, 64x64 KV tiles, skip tiles fully above diagonal.
 * 256 threads, 4x4 micro-tile per thread (16x16 thread grid).
 * ===================================================================== */
struct AttSmem {
    float Qs[64][64];   /* [d][r] transposed */
    float Ks[64][64];   /* [d][c] transposed */
    float Vs[64][64];   /* [t][c] natural    */
    float Ps[64][68];   /* [r][t] probs, padded for banks */
    float red[64][17];  /* row reductions    */
    float m_s[64];
    float l_s[64];
    float rscale[64];
};

__global__ void attn_kernel(const float* __restrict__ Q,
                            const float* __restrict__ K,
                            const float* __restrict__ V,
                            float* __restrict__ Out) {
    extern __shared__ unsigned char smem_raw[];
    AttSmem* sm = (AttSmem*)smem_raw;

    const int tid = threadIdx.x;
    const int qt  = blockIdx.x;       /* 0..31 */
    const int h   = blockIdx.y;       /* 0..70 */
    const int qs0 = qt * 64;
    const int r0  = (tid >> 4) * 4;
    const int c0  = (tid & 15) * 4;
    const int lrow  = tid >> 2;       /* 0..63 */
    const int dbase = (tid & 3) * 16;
    const int lx = tid & 15;

    /* load Q tile transposed */
    {
        const float* qg = Q + ((size_t)h * S_LEN + qs0 + lrow) * HDIM + dbase;
#pragma unroll
        for (int u = 0; u < 4; u++) {
            float4 t = *(const float4*)(qg + u * 4);
            sm->Qs[dbase + u * 4 + 0][lrow] = t.x;
            sm->Qs[dbase + u * 4 + 1][lrow] = t.y;
            sm->Qs[dbase + u * 4 + 2][lrow] = t.z;
            sm->Qs[dbase + u * 4 + 3][lrow] = t.w;
        }
    }
    if (tid < 64) { sm->m_s[tid] = -1e30f; sm->l_s[tid] = 0.0f; }

    float o[4][4];
#pragma unroll
    for (int i = 0; i < 4; i++)
#pragma unroll
        for (int j = 0; j < 4; j++) o[i][j] = 0.0f;

    for (int jt = 0; jt <= qt; jt++) {
        /* load K transposed + V natural */
        {
            const float* kg = K + (size_t)(jt * 64 + lrow) * HDIM + dbase;
            const float* vg = V + (size_t)(jt * 64 + lrow) * HDIM + dbase;
#pragma unroll
            for (int u = 0; u < 4; u++) {
                float4 t = *(const float4*)(kg + u * 4);
                sm->Ks[dbase + u * 4 + 0][lrow] = t.x;
                sm->Ks[dbase + u * 4 + 1][lrow] = t.y;
                sm->Ks[dbase + u * 4 + 2][lrow] = t.z;
                sm->Ks[dbase + u * 4 + 3][lrow] = t.w;
                float4 tv = *(const float4*)(vg + u * 4);
                *(float4*)&sm->Vs[lrow][dbase + u * 4] = tv;
            }
        }
        __syncthreads();

        /* S = Q K^T */
        float s[4][4];
#pragma unroll
        for (int i = 0; i < 4; i++)
#pragma unroll
            for (int j = 0; j < 4; j++) s[i][j] = 0.0f;

#pragma unroll 8
        for (int d = 0; d < 64; d++) {
            float4 qv = *(const float4*)&sm->Qs[d][r0];
            float4 kv = *(const float4*)&sm->Ks[d][c0];
            float qa[4] = {qv.x, qv.y, qv.z, qv.w};
            float ka[4] = {kv.x, kv.y, kv.z, kv.w};
#pragma unroll
            for (int i = 0; i < 4; i++)
#pragma unroll
                for (int j = 0; j < 4; j++) s[i][j] = fmaf(qa[i], ka[j], s[i][j]);
        }

        const float scale = 0.125f;  /* 1/sqrt(64) */
#pragma unroll
        for (int i = 0; i < 4; i++)
#pragma unroll
            for (int j = 0; j < 4; j++) s[i][j] *= scale;

        if (jt == qt) {
#pragma unroll
            for (int i = 0; i < 4; i++)
#pragma unroll
                for (int j = 0; j < 4; j++)
                    if (c0 + j > r0 + i) s[i][j] = -1e30f;
        }

        /* row max: partial per-thread, then 64-thread finalize */
#pragma unroll
        for (int i = 0; i < 4; i++) {
            float pm = fmaxf(fmaxf(s[i][0], s[i][1]), fmaxf(s[i][2], s[i][3]));
            sm->red[r0 + i][lx] = pm;
        }
        __syncthreads();
        if (tid < 64) {
            float mo = sm->m_s[tid];
            float mn = mo;
#pragma unroll
            for (int x = 0; x < 16; x++) mn = fmaxf(mn, sm->red[tid][x]);
            sm->rscale[tid] = __expf(mo - mn);
            sm->m_s[tid] = mn;
        }
        __syncthreads();

        /* exp + P write + partial sums */
        float psum[4];
#pragma unroll
        for (int i = 0; i < 4; i++) {
            float mn = sm->m_s[r0 + i];
            float e0 = __expf(s[i][0] - mn);
            float e1 = __expf(s[i][1] - mn);
            float e2 = __expf(s[i][2] - mn);
            float e3 = __expf(s[i][3] - mn);
            psum[i] = (e0 + e1) + (e2 + e3);
            *(float4*)&sm->Ps[r0 + i][c0] = make_float4(e0, e1, e2, e3);
        }
#pragma unroll
        for (int i = 0; i < 4; i++) sm->red[r0 + i][lx] = psum[i];
        __syncthreads();
        if (tid < 64) {
            float ss = 0.0f;
#pragma unroll
            for (int x = 0; x < 16; x++) ss += sm->red[tid][x];
            sm->l_s[tid] = sm->l_s[tid] * sm->rscale[tid] + ss;
        }
        __syncthreads();

        /* rescale O, then O += P V */
#pragma unroll
        for (int i = 0; i < 4; i++) {
            float rs = sm->rscale[r0 + i];
#pragma unroll
            for (int j = 0; j < 4; j++) o[i][j] *= rs;
        }

        for (int t0 = 0; t0 < 64; t0 += 4) {
            float pr[4][4];
#pragma unroll
            for (int i = 0; i < 4; i++)
                *(float4*)&pr[i][0] = *(const float4*)&sm->Ps[r0 + i][t0];
#pragma unroll
            for (int tt = 0; tt < 4; tt++) {
                float4 vv = *(const float4*)&sm->Vs[t0 + tt][c0];
                float va[4] = {vv.x, vv.y, vv.z, vv.w};
#pragma unroll
                for (int i = 0; i < 4; i++)
#pragma unroll
                    for (int j = 0; j < 4; j++)
                        o[i][j] = fmaf(pr[i][tt], va[j], o[i][j]);
            }
        }
        __syncthreads();
    }

    /* normalize + store to attn[s, h*64 + c] */
#pragma unroll
    for (int i = 0; i < 4; i++) {
        float inv = 1.0f / sm->l_s[r0 + i];
        float4 ov = make_float4(o[i][0] * inv, o[i][1] * inv, o[i][2] * inv, o[i][3] * inv);
        *(float4*)&Out[(size_t)(qs0 + r0 + i) * H_DIM + h * HDIM + c0] = ov;
    }
}

/* ===================================================================== */
extern "C" void kernel_launch(void* const* d_in, const int* in_sizes, int n_in,
                              void* d_out, int out_size) {
    const float* hidden  = (const float*)d_in[0];
    /* d_in[1] = attention_mask: exact causal, reproduced analytically */
    const float* qkv_w   = (const float*)d_in[2];
    const float* dense_w = (const float*)d_in[3];
    float* out = (float*)d_out;

    float *qkv_p, *q_p, *k_p, *v_p, *attn_p;
    cudaGetSymbolAddress((void**)&qkv_p,  g_qkv);
    cudaGetSymbolAddress((void**)&q_p,    g_q);
    cudaGetSymbolAddress((void**)&k_p,    g_k);
    cudaGetSymbolAddress((void**)&v_p,    g_v);
    cudaGetSymbolAddress((void**)&attn_p, g_attn);

    cudaFuncSetAttribute(attn_kernel, cudaFuncAttributeMaxDynamicSharedMemorySize,
                         (int)sizeof(AttSmem));

    /* 1) qkv = x @ qkv_w : [2048,4544]x[4544,4672] */
    sgemm_kernel<<<dim3(QKV_N / 64, S_LEN / 128), 256>>>(hidden, qkv_w, qkv_p,
                                                         S_LEN, QKV_N, H_DIM);
    /* 2) RoPE + split */
    rope_split_kernel<<<S_LEN, 256>>>(qkv_p, q_p, k_p, v_p);
    /* 3) causal attention */
    attn_kernel<<<dim3(S_LEN / 64, NHEAD), 256, sizeof(AttSmem)>>>(q_p, k_p, v_p, attn_p);
    /* 4) out = attn @ dense_w : [2048,4544]x[4544,4544] */
    sgemm_kernel<<<dim3(H_DIM / 64, S_LEN / 128), 256>>>(attn_p, dense_w, out,
                                                         S_LEN, H_DIM, H_DIM);
}

// round 3
// speedup vs baseline: 1.0020x; 1.0020x over previous
#include <cuda_runtime.h>
#include <cuda_bf16.h>
#include <math.h>

#define S_LEN 2048
#define NHEAD 71
#define HDIM  64
#define H_DIM (NHEAD * HDIM)          /* 4544 */
#define QKV_N ((NHEAD + 2) * HDIM)    /* 4672 */

/* ---- scratch (no allocs allowed: __device__ globals) ---- */
__device__ float g_qkv[(size_t)S_LEN * QKV_N];           /* 38 MB */
__device__ float g_q[(size_t)NHEAD * S_LEN * HDIM];      /* 37 MB, head-major */
__device__ float g_k[(size_t)S_LEN * HDIM];
__device__ float g_v[(size_t)S_LEN * HDIM];
__device__ float g_attn[(size_t)S_LEN * H_DIM];          /* 37 MB */

/* =====================================================================
 * SGEMM: C[M,N] = A[M,K] * B[K,N]  (row-major), BM=128 BN=64 BK=16,
 * 256 threads, 8x4 micro-tile per thread. M%128==0, N%64==0, K%16==0.
 * ===================================================================== */
__global__ void sgemm_kernel(const float* __restrict__ A,
                             const float* __restrict__ B,
                             float* __restrict__ C,
                             int M, int N, int K) {
    __shared__ float As[16][132];   /* transposed A tile, padded */
    __shared__ float Bs[16][64];

    const int tid    = threadIdx.x;
    const int rowBlk = blockIdx.y * 128;
    const int colBlk = blockIdx.x * 64;
    const int r0 = (tid >> 4) * 8;      /* 0..120 */
    const int c0 = (tid & 15) * 4;      /* 0..60  */
    const int aRow = tid >> 2;          /* 0..63  */
    const int aCol = (tid & 3) * 4;     /* 0,4,8,12 */
    const int bRow = tid >> 4;          /* 0..15  */
    const int bCol = (tid & 15) * 4;

    const float* Ap = A + (size_t)(rowBlk + aRow) * K + aCol;
    const float* Bp = B + (size_t)bRow * N + colBlk + bCol;

    float acc[8][4];
#pragma unroll
    for (int i = 0; i < 8; i++)
#pragma unroll
        for (int j = 0; j < 4; j++) acc[i][j] = 0.0f;

    for (int k0 = 0; k0 < K; k0 += 16) {
        float4 a0 = *(const float4*)Ap;
        float4 a1 = *(const float4*)(Ap + (size_t)64 * K);
        float4 b0 = *(const float4*)Bp;

        As[aCol + 0][aRow] = a0.x;
        As[aCol + 1][aRow] = a0.y;
        As[aCol + 2][aRow] = a0.z;
        As[aCol + 3][aRow] = a0.w;
        As[aCol + 0][aRow + 64] = a1.x;
        As[aCol + 1][aRow + 64] = a1.y;
        As[aCol + 2][aRow + 64] = a1.z;
        As[aCol + 3][aRow + 64] = a1.w;
        *(float4*)&Bs[bRow][bCol] = b0;
        __syncthreads();

#pragma unroll
        for (int kk = 0; kk < 16; kk++) {
            float4 av0 = *(const float4*)&As[kk][r0];
            float4 av1 = *(const float4*)&As[kk][r0 + 4];
            float4 bv  = *(const float4*)&Bs[kk][c0];
            float a[8] = {av0.x, av0.y, av0.z, av0.w, av1.x, av1.y, av1.z, av1.w};
            float b[4] = {bv.x, bv.y, bv.z, bv.w};
#pragma unroll
            for (int i = 0; i < 8; i++)
#pragma unroll
                for (int j = 0; j < 4; j++) acc[i][j] = fmaf(a[i], b[j], acc[i][j]);
        }
        __syncthreads();
        Ap += 16;
        Bp += (size_t)16 * N;
    }

#pragma unroll
    for (int i = 0; i < 8; i++) {
        float4 o = make_float4(acc[i][0], acc[i][1], acc[i][2], acc[i][3]);
        *(float4*)&C[(size_t)(rowBlk + r0 + i) * N + colBlk + c0] = o;
    }
}

/* =====================================================================
 * RoPE + split: qkv[2048, 4672] -> q[h][s][d] (roped), k[s][d] (roped),
 * v[s][d] (raw). Freqs: angle = s * 10000^(-(d%32)/32).
 * ===================================================================== */
__global__ void rope_split_kernel(const float* __restrict__ qkv,
                                  float* __restrict__ q,
                                  float* __restrict__ k,
                                  float* __restrict__ v) {
    const int s = blockIdx.x;
    const float* row = qkv + (size_t)s * QKV_N;
    const float fs = (float)s;
    const float L2C = 13.28771237954945f / 32.0f;   /* log2(10000)/32 */

    for (int col = threadIdx.x; col < QKV_N; col += blockDim.x) {
        const int h = col >> 6;
        const int d = col & 63;
        float val = row[col];
        if (h < NHEAD + 1) {
            const int jj = d & 31;
            float inv = exp2f(-(float)jj * L2C);
            float ang = fs * inv;
            float sn, cs;
            sincosf(ang, &sn, &cs);
            float other = (d < 32) ? -row[h * 64 + d + 32] : row[h * 64 + d - 32];
            float o = val * cs + other * sn;
            if (h < NHEAD)
                q[((size_t)h * S_LEN + s) * HDIM + d] = o;
            else
                k[(size_t)s * HDIM + d] = o;
        } else {
            v[(size_t)s * HDIM + d] = val;
        }
    }
}

/* =====================================================================
 * Flash-style causal attention. Block = (q-tile of 64 rows, head).
 * Online softmax, 64x64 KV tiles, skip tiles fully above diagonal.
 * 256 threads, 4x4 micro-tile per thread (16x16 thread grid).
 * ===================================================================== */
struct AttSmem {
    float Qs[64][64];   /* [d][r] transposed */
    float Ks[64][64];   /* [d][c] transposed */
    float Vs[64][64];   /* [t][c] natural    */
    float Ps[64][68];   /* [r][t] probs, padded for banks */
    float red[64][17];  /* row reductions    */
    float m_s[64];
    float l_s[64];
    float rscale[64];
};

__global__ void attn_kernel(const float* __restrict__ Q,
                            const float* __restrict__ K,
                            const float* __restrict__ V,
                            float* __restrict__ Out) {
    extern __shared__ unsigned char smem_raw[];
    AttSmem* sm = (AttSmem*)smem_raw;

    const int tid = threadIdx.x;
    const int qt  = blockIdx.x;       /* 0..31 */
    const int h   = blockIdx.y;       /* 0..70 */
    const int qs0 = qt * 64;
    const int r0  = (tid >> 4) * 4;
    const int c0  = (tid & 15) * 4;
    const int lrow  = tid >> 2;       /* 0..63 */
    const int dbase = (tid & 3) * 16;
    const int lx = tid & 15;

    /* load Q tile transposed */
    {
        const float* qg = Q + ((size_t)h * S_LEN + qs0 + lrow) * HDIM + dbase;
#pragma unroll
        for (int u = 0; u < 4; u++) {
            float4 t = *(const float4*)(qg + u * 4);
            sm->Qs[dbase + u * 4 + 0][lrow] = t.x;
            sm->Qs[dbase + u * 4 + 1][lrow] = t.y;
            sm->Qs[dbase + u * 4 + 2][lrow] = t.z;
            sm->Qs[dbase + u * 4 + 3][lrow] = t.w;
        }
    }
    if (tid < 64) { sm->m_s[tid] = -1e30f; sm->l_s[tid] = 0.0f; }

    float o[4][4];
#pragma unroll
    for (int i = 0; i < 4; i++)
#pragma unroll
        for (int j = 0; j < 4; j++) o[i][j] = 0.0f;

    for (int jt = 0; jt <= qt; jt++) {
        /* load K transposed + V natural */
        {
            const float* kg = K + (size_t)(jt * 64 + lrow) * HDIM + dbase;
            const float* vg = V + (size_t)(jt * 64 + lrow) * HDIM + dbase;
#pragma unroll
            for (int u = 0; u < 4; u++) {
                float4 t = *(const float4*)(kg + u * 4);
                sm->Ks[dbase + u * 4 + 0][lrow] = t.x;
                sm->Ks[dbase + u * 4 + 1][lrow] = t.y;
                sm->Ks[dbase + u * 4 + 2][lrow] = t.z;
                sm->Ks[dbase + u * 4 + 3][lrow] = t.w;
                float4 tv = *(const float4*)(vg + u * 4);
                *(float4*)&sm->Vs[lrow][dbase + u * 4] = tv;
            }
        }
        __syncthreads();

        /* S = Q K^T */
        float s[4][4];
#pragma unroll
        for (int i = 0; i < 4; i++)
#pragma unroll
            for (int j = 0; j < 4; j++) s[i][j] = 0.0f;

#pragma unroll 8
        for (int d = 0; d < 64; d++) {
            float4 qv = *(const float4*)&sm->Qs[d][r0];
            float4 kv = *(const float4*)&sm->Ks[d][c0];
            float qa[4] = {qv.x, qv.y, qv.z, qv.w};
            float ka[4] = {kv.x, kv.y, kv.z, kv.w};
#pragma unroll
            for (int i = 0; i < 4; i++)
#pragma unroll
                for (int j = 0; j < 4; j++) s[i][j] = fmaf(qa[i], ka[j], s[i][j]);
        }

        const float scale = 0.125f;  /* 1/sqrt(64) */
#pragma unroll
        for (int i = 0; i < 4; i++)
#pragma unroll
            for (int j = 0; j < 4; j++) s[i][j] *= scale;

        if (jt == qt) {
#pragma unroll
            for (int i = 0; i < 4; i++)
#pragma unroll
                for (int j = 0; j < 4; j++)
                    if (c0 + j > r0 + i) s[i][j] = -1e30f;
        }

        /* row max: partial per-thread, then 64-thread finalize */
#pragma unroll
        for (int i = 0; i < 4; i++) {
            float pm = fmaxf(fmaxf(s[i][0], s[i][1]), fmaxf(s[i][2], s[i][3]));
            sm->red[r0 + i][lx] = pm;
        }
        __syncthreads();
        if (tid < 64) {
            float mo = sm->m_s[tid];
            float mn = mo;
#pragma unroll
            for (int x = 0; x < 16; x++) mn = fmaxf(mn, sm->red[tid][x]);
            sm->rscale[tid] = __expf(mo - mn);
            sm->m_s[tid] = mn;
        }
        __syncthreads();

        /* exp + P write + partial sums */
        float psum[4];
#pragma unroll
        for (int i = 0; i < 4; i++) {
            float mn = sm->m_s[r0 + i];
            float e0 = __expf(s[i][0] - mn);
            float e1 = __expf(s[i][1] - mn);
            float e2 = __expf(s[i][2] - mn);
            float e3 = __expf(s[i][3] - mn);
            psum[i] = (e0 + e1) + (e2 + e3);
            *(float4*)&sm->Ps[r0 + i][c0] = make_float4(e0, e1, e2, e3);
        }
#pragma unroll
        for (int i = 0; i < 4; i++) sm->red[r0 + i][lx] = psum[i];
        __syncthreads();
        if (tid < 64) {
            float ss = 0.0f;
#pragma unroll
            for (int x = 0; x < 16; x++) ss += sm->red[tid][x];
            sm->l_s[tid] = sm->l_s[tid] * sm->rscale[tid] + ss;
        }
        __syncthreads();

        /* rescale O, then O += P V */
#pragma unroll
        for (int i = 0; i < 4; i++) {
            float rs = sm->rscale[r0 + i];
#pragma unroll
            for (int j = 0; j < 4; j++) o[i][j] *= rs;
        }

        for (int t0 = 0; t0 < 64; t0 += 4) {
            float pr[4][4];
#pragma unroll
            for (int i = 0; i < 4; i++)
                *(float4*)&pr[i][0] = *(const float4*)&sm->Ps[r0 + i][t0];
#pragma unroll
            for (int tt = 0; tt < 4; tt++) {
                float4 vv = *(const float4*)&sm->Vs[t0 + tt][c0];
                float va[4] = {vv.x, vv.y, vv.z, vv.w};
#pragma unroll
                for (int i = 0; i < 4; i++)
#pragma unroll
                    for (int j = 0; j < 4; j++)
                        o[i][j] = fmaf(pr[i][tt], va[j], o[i][j]);
            }
        }
        __syncthreads();
    }

    /* normalize + store to attn[s, h*64 + c] */
#pragma unroll
    for (int i = 0; i < 4; i++) {
        float inv = 1.0f / sm->l_s[r0 + i];
        float4 ov = make_float4(o[i][0] * inv, o[i][1] * inv, o[i][2] * inv, o[i][3] * inv);
        *(float4*)&Out[(size_t)(qs0 + r0 + i) * H_DIM + h * HDIM + c0] = ov;
    }
}

/* ===================================================================== */
extern "C" void kernel_launch(void* const* d_in, const int* in_sizes, int n_in,
                              void* d_out, int out_size) {
    const float* hidden  = (const float*)d_in[0];
    /* d_in[1] = attention_mask: exact causal, reproduced analytically */
    const float* qkv_w   = (const float*)d_in[2];
    const float* dense_w = (const float*)d_in[3];
    float* out = (float*)d_out;

    float *qkv_p, *q_p, *k_p, *v_p, *attn_p;
    cudaGetSymbolAddress((void**)&qkv_p,  g_qkv);
    cudaGetSymbolAddress((void**)&q_p,    g_q);
    cudaGetSymbolAddress((void**)&k_p,    g_k);
    cudaGetSymbolAddress((void**)&v_p,    g_v);
    cudaGetSymbolAddress((void**)&attn_p, g_attn);

    cudaFuncSetAttribute(attn_kernel, cudaFuncAttributeMaxDynamicSharedMemorySize,
                         (int)sizeof(AttSmem));

    /* 1) qkv = x @ qkv_w : [2048,4544]x[4544,4672] */
    sgemm_kernel<<<dim3(QKV_N / 64, S_LEN / 128), 256>>>(hidden, qkv_w, qkv_p,
                                                         S_LEN, QKV_N, H_DIM);
    /* 2) RoPE + split */
    rope_split_kernel<<<S_LEN, 256>>>(qkv_p, q_p, k_p, v_p);
    /* 3) causal attention */
    attn_kernel<<<dim3(S_LEN / 64, NHEAD), 256, sizeof(AttSmem)>>>(q_p, k_p, v_p, attn_p);
    /* 4) out = attn @ dense_w : [2048,4544]x[4544,4544] */
    sgemm_kernel<<<dim3(H_DIM / 64, S_LEN / 128), 256>>>(attn_p, dense_w, out,
                                                         S_LEN, H_DIM, H_DIM);
}

// round 4
// speedup vs baseline: 1.7041x; 1.7007x over previous
#include <cuda_runtime.h>
#include <cuda_bf16.h>
#include <math.h>
#include <stdint.h>

#define S_LEN 2048
#define NHEAD 71
#define HDIM  64
#define H_DIM (NHEAD * HDIM)          /* 4544 */
#define QKV_N ((NHEAD + 2) * HDIM)    /* 4672 */

/* ---- fp32 scratch ---- */
__device__ float g_qkv[(size_t)S_LEN * QKV_N];
__device__ float g_q[(size_t)NHEAD * S_LEN * HDIM];
__device__ float g_k[(size_t)S_LEN * HDIM];
__device__ float g_v[(size_t)S_LEN * HDIM];
__device__ float g_attn[(size_t)S_LEN * H_DIM];

/* ---- bf16 hi/lo split scratch (16B aligned for uint4 loads) ---- */
__device__ __align__(256) __nv_bfloat16 g_xh[(size_t)S_LEN * H_DIM];
__device__ __align__(256) __nv_bfloat16 g_xl[(size_t)S_LEN * H_DIM];
__device__ __align__(256) __nv_bfloat16 g_wqh[(size_t)H_DIM * QKV_N];
__device__ __align__(256) __nv_bfloat16 g_wql[(size_t)H_DIM * QKV_N];
__device__ __align__(256) __nv_bfloat16 g_wdh[(size_t)H_DIM * H_DIM];
__device__ __align__(256) __nv_bfloat16 g_wdl[(size_t)H_DIM * H_DIM];
__device__ __align__(256) __nv_bfloat16 g_ah[(size_t)S_LEN * H_DIM];
__device__ __align__(256) __nv_bfloat16 g_al[(size_t)S_LEN * H_DIM];

/* =====================================================================
 * fp32 -> (bf16 hi, bf16 lo) split, vectorized by 4.
 * ===================================================================== */
__global__ void split4_kernel(const float* __restrict__ x,
                              __nv_bfloat16* __restrict__ hi,
                              __nv_bfloat16* __restrict__ lo,
                              int n4) {
    int i = blockIdx.x * blockDim.x + threadIdx.x;
    if (i >= n4) return;
    float4 v = ((const float4*)x)[i];
    float vv[4] = {v.x, v.y, v.z, v.w};
    __nv_bfloat16 h[4], l[4];
#pragma unroll
    for (int j = 0; j < 4; j++) {
        h[j] = __float2bfloat16(vv[j]);
        l[j] = __float2bfloat16(vv[j] - __bfloat162float(h[j]));
    }
    ((__nv_bfloat162*)hi)[2 * i + 0] = __nv_bfloat162(h[0], h[1]);
    ((__nv_bfloat162*)hi)[2 * i + 1] = __nv_bfloat162(h[2], h[3]);
    ((__nv_bfloat162*)lo)[2 * i + 0] = __nv_bfloat162(l[0], l[1]);
    ((__nv_bfloat162*)lo)[2 * i + 1] = __nv_bfloat162(l[2], l[3]);
}

/* ---- mma helpers ---- */
__device__ __forceinline__ void ldm_x4(uint32_t* r, uint32_t addr) {
    asm volatile("ldmatrix.sync.aligned.m8n8.x4.shared.b16 {%0,%1,%2,%3}, [%4];\n"
                 : "=r"(r[0]), "=r"(r[1]), "=r"(r[2]), "=r"(r[3]) : "r"(addr));
}
__device__ __forceinline__ void ldm_x4_t(uint32_t* r, uint32_t addr) {
    asm volatile("ldmatrix.sync.aligned.m8n8.x4.trans.shared.b16 {%0,%1,%2,%3}, [%4];\n"
                 : "=r"(r[0]), "=r"(r[1]), "=r"(r[2]), "=r"(r[3]) : "r"(addr));
}
__device__ __forceinline__ void mma_bf16(float* c, const uint32_t* a, const uint32_t* b) {
    asm volatile(
        "mma.sync.aligned.m16n8k16.row.col.f32.bf16.bf16.f32 "
        "{%0,%1,%2,%3}, {%4,%5,%6,%7}, {%8,%9}, {%0,%1,%2,%3};\n"
        : "+f"(c[0]), "+f"(c[1]), "+f"(c[2]), "+f"(c[3])
        : "r"(a[0]), "r"(a[1]), "r"(a[2]), "r"(a[3]), "r"(b[0]), "r"(b[1]));
}

/* =====================================================================
 * Split-bf16 GEMM: C[M,N](fp32) = A*B with A = Ah+Al, B = Bh+Bl (bf16).
 * Computes Ah*Bh + Ah*Bl + Al*Bh into fp32 accumulators (tensor cores).
 * BM=128 BN=64 BK=32, 256 threads (8 warps: 4x2 of 32x32 warp tiles).
 * Requires M%128==0, N%64==0, K%32==0.
 * ===================================================================== */
#define APAD 40   /* bf16 row pitch for A smem (80B, ldmatrix conflict-free) */
#define BPAD 72   /* bf16 row pitch for B smem (144B, conflict-free) */

__global__ void __launch_bounds__(256)
gemm_bf16split_kernel(const __nv_bfloat16* __restrict__ Ah,
                      const __nv_bfloat16* __restrict__ Al,
                      const __nv_bfloat16* __restrict__ Bh,
                      const __nv_bfloat16* __restrict__ Bl,
                      float* __restrict__ C,
                      int M, int N, int K) {
    __shared__ __nv_bfloat16 As[2][128][APAD];
    __shared__ __nv_bfloat16 Bs[2][32][BPAD];

    const int tid  = threadIdx.x;
    const int lane = tid & 31;
    const int wid  = tid >> 5;
    const int wm   = (wid & 3) * 32;
    const int wn   = (wid >> 2) * 32;
    const int rowBlk = blockIdx.y * 128;
    const int colBlk = blockIdx.x * 64;

    /* gmem load mapping */
    const int ar0 = tid >> 2;                 /* uint4 idx tid   -> row */
    const int ac0 = (tid & 3) * 8;
    const int ar1 = (tid + 256) >> 2;         /* uint4 idx tid+256 */
    const int ac1 = ((tid + 256) & 3) * 8;
    const int br  = tid >> 3;
    const int bc  = (tid & 7) * 8;

    const __nv_bfloat16* Ah0 = Ah + (size_t)(rowBlk + ar0) * K + ac0;
    const __nv_bfloat16* Ah1 = Ah + (size_t)(rowBlk + ar1) * K + ac1;
    const __nv_bfloat16* Al0 = Al + (size_t)(rowBlk + ar0) * K + ac0;
    const __nv_bfloat16* Al1 = Al + (size_t)(rowBlk + ar1) * K + ac1;
    const __nv_bfloat16* Bh0 = Bh + (size_t)br * N + colBlk + bc;
    const __nv_bfloat16* Bl0 = Bl + (size_t)br * N + colBlk + bc;

    uint32_t sA = (uint32_t)__cvta_generic_to_shared(&As[0][0][0]);
    uint32_t sB = (uint32_t)__cvta_generic_to_shared(&Bs[0][0][0]);

    const int lr = lane & 15;
    const int lc = (lane >> 4) << 3;

    float acc[2][4][4];
#pragma unroll
    for (int mt = 0; mt < 2; mt++)
#pragma unroll
        for (int nt = 0; nt < 4; nt++)
#pragma unroll
            for (int r = 0; r < 4; r++) acc[mt][nt][r] = 0.0f;

    const int iters = K / 32;
    uint4 pa_h0, pa_h1, pa_l0, pa_l1, pb_h, pb_l;

    /* prefetch iter 0 */
    pa_h0 = *(const uint4*)Ah0;  pa_h1 = *(const uint4*)Ah1;
    pa_l0 = *(const uint4*)Al0;  pa_l1 = *(const uint4*)Al1;
    pb_h  = *(const uint4*)Bh0;  pb_l  = *(const uint4*)Bl0;

    for (int it = 0; it < iters; it++) {
        /* store prefetched regs to smem */
        *(uint4*)&As[0][ar0][ac0] = pa_h0;
        *(uint4*)&As[0][ar1][ac1] = pa_h1;
        *(uint4*)&As[1][ar0][ac0] = pa_l0;
        *(uint4*)&As[1][ar1][ac1] = pa_l1;
        *(uint4*)&Bs[0][br][bc]   = pb_h;
        *(uint4*)&Bs[1][br][bc]   = pb_l;
        __syncthreads();

        /* prefetch next iter from gmem (overlaps with mma below) */
        if (it + 1 < iters) {
            int ko = (it + 1) * 32;
            pa_h0 = *(const uint4*)(Ah0 + ko);  pa_h1 = *(const uint4*)(Ah1 + ko);
            pa_l0 = *(const uint4*)(Al0 + ko);  pa_l1 = *(const uint4*)(Al1 + ko);
            pb_h  = *(const uint4*)(Bh0 + (size_t)ko * N);
            pb_l  = *(const uint4*)(Bl0 + (size_t)ko * N);
        }

#pragma unroll
        for (int kk = 0; kk < 32; kk += 16) {
            uint32_t ah[2][4], al[2][4], bh[4][2], bl[4][2];
#pragma unroll
            for (int mt = 0; mt < 2; mt++) {
                uint32_t arow = (uint32_t)(wm + mt * 16 + lr);
                uint32_t acol = (uint32_t)(kk + lc);
                ldm_x4(ah[mt], sA + (arow * APAD + acol) * 2);
                ldm_x4(al[mt], sA + ((128 + arow) * APAD + acol) * 2);
            }
#pragma unroll
            for (int half = 0; half < 2; half++) {
                uint32_t brow = (uint32_t)(kk + lr);
                uint32_t bcol = (uint32_t)(wn + half * 16 + lc);
                uint32_t r[4];
                ldm_x4_t(r, sB + (brow * BPAD + bcol) * 2);
                bh[half * 2 + 0][0] = r[0]; bh[half * 2 + 0][1] = r[1];
                bh[half * 2 + 1][0] = r[2]; bh[half * 2 + 1][1] = r[3];
                ldm_x4_t(r, sB + ((32 + brow) * BPAD + bcol) * 2);
                bl[half * 2 + 0][0] = r[0]; bl[half * 2 + 0][1] = r[1];
                bl[half * 2 + 1][0] = r[2]; bl[half * 2 + 1][1] = r[3];
            }
#pragma unroll
            for (int mt = 0; mt < 2; mt++)
#pragma unroll
                for (int nt = 0; nt < 4; nt++) {
                    mma_bf16(acc[mt][nt], ah[mt], bh[nt]);
                    mma_bf16(acc[mt][nt], ah[mt], bl[nt]);
                    mma_bf16(acc[mt][nt], al[mt], bh[nt]);
                }
        }
        __syncthreads();
    }

    /* epilogue */
#pragma unroll
    for (int mt = 0; mt < 2; mt++) {
        int row = rowBlk + wm + mt * 16 + (lane >> 2);
#pragma unroll
        for (int nt = 0; nt < 4; nt++) {
            int col = colBlk + wn + nt * 8 + (lane & 3) * 2;
            *(float2*)&C[(size_t)row * N + col] =
                make_float2(acc[mt][nt][0], acc[mt][nt][1]);
            *(float2*)&C[(size_t)(row + 8) * N + col] =
                make_float2(acc[mt][nt][2], acc[mt][nt][3]);
        }
    }
}

/* =====================================================================
 * RoPE + split (unchanged)
 * ===================================================================== */
__global__ void rope_split_kernel(const float* __restrict__ qkv,
                                  float* __restrict__ q,
                                  float* __restrict__ k,
                                  float* __restrict__ v) {
    const int s = blockIdx.x;
    const float* row = qkv + (size_t)s * QKV_N;
    const float fs = (float)s;
    const float L2C = 13.28771237954945f / 32.0f;

    for (int col = threadIdx.x; col < QKV_N; col += blockDim.x) {
        const int h = col >> 6;
        const int d = col & 63;
        float val = row[col];
        if (h < NHEAD + 1) {
            const int jj = d & 31;
            float inv = exp2f(-(float)jj * L2C);
            float ang = fs * inv;
            float sn, cs;
            sincosf(ang, &sn, &cs);
            float other = (d < 32) ? -row[h * 64 + d + 32] : row[h * 64 + d - 32];
            float o = val * cs + other * sn;
            if (h < NHEAD)
                q[((size_t)h * S_LEN + s) * HDIM + d] = o;
            else
                k[(size_t)s * HDIM + d] = o;
        } else {
            v[(size_t)s * HDIM + d] = val;
        }
    }
}

/* =====================================================================
 * Flash-style causal attention (unchanged from R2)
 * ===================================================================== */
struct AttSmem {
    float Qs[64][64];
    float Ks[64][64];
    float Vs[64][64];
    float Ps[64][68];
    float red[64][17];
    float m_s[64];
    float l_s[64];
    float rscale[64];
};

__global__ void attn_kernel(const float* __restrict__ Q,
                            const float* __restrict__ K,
                            const float* __restrict__ V,
                            float* __restrict__ Out) {
    extern __shared__ unsigned char smem_raw[];
    AttSmem* sm = (AttSmem*)smem_raw;

    const int tid = threadIdx.x;
    const int qt  = blockIdx.x;
    const int h   = blockIdx.y;
    const int qs0 = qt * 64;
    const int r0  = (tid >> 4) * 4;
    const int c0  = (tid & 15) * 4;
    const int lrow  = tid >> 2;
    const int dbase = (tid & 3) * 16;
    const int lx = tid & 15;

    {
        const float* qg = Q + ((size_t)h * S_LEN + qs0 + lrow) * HDIM + dbase;
#pragma unroll
        for (int u = 0; u < 4; u++) {
            float4 t = *(const float4*)(qg + u * 4);
            sm->Qs[dbase + u * 4 + 0][lrow] = t.x;
            sm->Qs[dbase + u * 4 + 1][lrow] = t.y;
            sm->Qs[dbase + u * 4 + 2][lrow] = t.z;
            sm->Qs[dbase + u * 4 + 3][lrow] = t.w;
        }
    }
    if (tid < 64) { sm->m_s[tid] = -1e30f; sm->l_s[tid] = 0.0f; }

    float o[4][4];
#pragma unroll
    for (int i = 0; i < 4; i++)
#pragma unroll
        for (int j = 0; j < 4; j++) o[i][j] = 0.0f;

    for (int jt = 0; jt <= qt; jt++) {
        {
            const float* kg = K + (size_t)(jt * 64 + lrow) * HDIM + dbase;
            const float* vg = V + (size_t)(jt * 64 + lrow) * HDIM + dbase;
#pragma unroll
            for (int u = 0; u < 4; u++) {
                float4 t = *(const float4*)(kg + u * 4);
                sm->Ks[dbase + u * 4 + 0][lrow] = t.x;
                sm->Ks[dbase + u * 4 + 1][lrow] = t.y;
                sm->Ks[dbase + u * 4 + 2][lrow] = t.z;
                sm->Ks[dbase + u * 4 + 3][lrow] = t.w;
                float4 tv = *(const float4*)(vg + u * 4);
                *(float4*)&sm->Vs[lrow][dbase + u * 4] = tv;
            }
        }
        __syncthreads();

        float s[4][4];
#pragma unroll
        for (int i = 0; i < 4; i++)
#pragma unroll
            for (int j = 0; j < 4; j++) s[i][j] = 0.0f;

#pragma unroll 8
        for (int d = 0; d < 64; d++) {
            float4 qv = *(const float4*)&sm->Qs[d][r0];
            float4 kv = *(const float4*)&sm->Ks[d][c0];
            float qa[4] = {qv.x, qv.y, qv.z, qv.w};
            float ka[4] = {kv.x, kv.y, kv.z, kv.w};
#pragma unroll
            for (int i = 0; i < 4; i++)
#pragma unroll
                for (int j = 0; j < 4; j++) s[i][j] = fmaf(qa[i], ka[j], s[i][j]);
        }

        const float scale = 0.125f;
#pragma unroll
        for (int i = 0; i < 4; i++)
#pragma unroll
            for (int j = 0; j < 4; j++) s[i][j] *= scale;

        if (jt == qt) {
#pragma unroll
            for (int i = 0; i < 4; i++)
#pragma unroll
                for (int j = 0; j < 4; j++)
                    if (c0 + j > r0 + i) s[i][j] = -1e30f;
        }

#pragma unroll
        for (int i = 0; i < 4; i++) {
            float pm = fmaxf(fmaxf(s[i][0], s[i][1]), fmaxf(s[i][2], s[i][3]));
            sm->red[r0 + i][lx] = pm;
        }
        __syncthreads();
        if (tid < 64) {
            float mo = sm->m_s[tid];
            float mn = mo;
#pragma unroll
            for (int x = 0; x < 16; x++) mn = fmaxf(mn, sm->red[tid][x]);
            sm->rscale[tid] = __expf(mo - mn);
            sm->m_s[tid] = mn;
        }
        __syncthreads();

        float psum[4];
#pragma unroll
        for (int i = 0; i < 4; i++) {
            float mn = sm->m_s[r0 + i];
            float e0 = __expf(s[i][0] - mn);
            float e1 = __expf(s[i][1] - mn);
            float e2 = __expf(s[i][2] - mn);
            float e3 = __expf(s[i][3] - mn);
            psum[i] = (e0 + e1) + (e2 + e3);
            *(float4*)&sm->Ps[r0 + i][c0] = make_float4(e0, e1, e2, e3);
        }
#pragma unroll
        for (int i = 0; i < 4; i++) sm->red[r0 + i][lx] = psum[i];
        __syncthreads();
        if (tid < 64) {
            float ss = 0.0f;
#pragma unroll
            for (int x = 0; x < 16; x++) ss += sm->red[tid][x];
            sm->l_s[tid] = sm->l_s[tid] * sm->rscale[tid] + ss;
        }
        __syncthreads();

#pragma unroll
        for (int i = 0; i < 4; i++) {
            float rs = sm->rscale[r0 + i];
#pragma unroll
            for (int j = 0; j < 4; j++) o[i][j] *= rs;
        }

        for (int t0 = 0; t0 < 64; t0 += 4) {
            float pr[4][4];
#pragma unroll
            for (int i = 0; i < 4; i++)
                *(float4*)&pr[i][0] = *(const float4*)&sm->Ps[r0 + i][t0];
#pragma unroll
            for (int tt = 0; tt < 4; tt++) {
                float4 vv = *(const float4*)&sm->Vs[t0 + tt][c0];
                float va[4] = {vv.x, vv.y, vv.z, vv.w};
#pragma unroll
                for (int i = 0; i < 4; i++)
#pragma unroll
                    for (int j = 0; j < 4; j++)
                        o[i][j] = fmaf(pr[i][tt], va[j], o[i][j]);
            }
        }
        __syncthreads();
    }

#pragma unroll
    for (int i = 0; i < 4; i++) {
        float inv = 1.0f / sm->l_s[r0 + i];
        float4 ov = make_float4(o[i][0] * inv, o[i][1] * inv, o[i][2] * inv, o[i][3] * inv);
        *(float4*)&Out[(size_t)(qs0 + r0 + i) * H_DIM + h * HDIM + c0] = ov;
    }
}

/* ===================================================================== */
extern "C" void kernel_launch(void* const* d_in, const int* in_sizes, int n_in,
                              void* d_out, int out_size) {
    const float* hidden  = (const float*)d_in[0];
    const float* qkv_w   = (const float*)d_in[2];
    const float* dense_w = (const float*)d_in[3];
    float* out = (float*)d_out;

    float *qkv_p, *q_p, *k_p, *v_p, *attn_p;
    cudaGetSymbolAddress((void**)&qkv_p,  g_qkv);
    cudaGetSymbolAddress((void**)&q_p,    g_q);
    cudaGetSymbolAddress((void**)&k_p,    g_k);
    cudaGetSymbolAddress((void**)&v_p,    g_v);
    cudaGetSymbolAddress((void**)&attn_p, g_attn);

    __nv_bfloat16 *xh, *xl, *wqh, *wql, *wdh, *wdl, *ah, *al;
    cudaGetSymbolAddress((void**)&xh,  g_xh);
    cudaGetSymbolAddress((void**)&xl,  g_xl);
    cudaGetSymbolAddress((void**)&wqh, g_wqh);
    cudaGetSymbolAddress((void**)&wql, g_wql);
    cudaGetSymbolAddress((void**)&wdh, g_wdh);
    cudaGetSymbolAddress((void**)&wdl, g_wdl);
    cudaGetSymbolAddress((void**)&ah,  g_ah);
    cudaGetSymbolAddress((void**)&al,  g_al);

    cudaFuncSetAttribute(attn_kernel, cudaFuncAttributeMaxDynamicSharedMemorySize,
                         (int)sizeof(AttSmem));

    /* 0) split inputs/weights to bf16 hi/lo */
    {
        int n4;
        n4 = (S_LEN * H_DIM) / 4;
        split4_kernel<<<(n4 + 255) / 256, 256>>>(hidden, xh, xl, n4);
        n4 = (H_DIM * QKV_N) / 4;
        split4_kernel<<<(n4 + 255) / 256, 256>>>(qkv_w, wqh, wql, n4);
        n4 = (H_DIM * H_DIM) / 4;
        split4_kernel<<<(n4 + 255) / 256, 256>>>(dense_w, wdh, wdl, n4);
    }

    /* 1) qkv = x @ qkv_w via split-bf16 tensor cores */
    gemm_bf16split_kernel<<<dim3(QKV_N / 64, S_LEN / 128), 256>>>(
        xh, xl, wqh, wql, qkv_p, S_LEN, QKV_N, H_DIM);

    /* 2) RoPE + split */
    rope_split_kernel<<<S_LEN, 256>>>(qkv_p, q_p, k_p, v_p);

    /* 3) causal attention (fp32) */
    attn_kernel<<<dim3(S_LEN / 64, NHEAD), 256, sizeof(AttSmem)>>>(q_p, k_p, v_p, attn_p);

    /* 4) split attn, then out = attn @ dense_w */
    {
        int n4 = (S_LEN * H_DIM) / 4;
        split4_kernel<<<(n4 + 255) / 256, 256>>>(attn_p, ah, al, n4);
    }
    gemm_bf16split_kernel<<<dim3(H_DIM / 64, S_LEN / 128), 256>>>(
        ah, al, wdh, wdl, out, S_LEN, H_DIM, H_DIM);
}

// round 5
// speedup vs baseline: 2.4730x; 1.4512x over previous
#include <cuda_runtime.h>
#include <cuda_bf16.h>
#include <math.h>
#include <stdint.h>

#define S_LEN 2048
#define NHEAD 71
#define HDIM  64
#define H_DIM (NHEAD * HDIM)          /* 4544 */
#define QKV_N ((NHEAD + 2) * HDIM)    /* 4672 */

/* ---- scratch (__device__ globals; no allocs allowed) ---- */
__device__ float g_qkv[(size_t)S_LEN * QKV_N];

__device__ __align__(256) __nv_bfloat16 g_xh[(size_t)S_LEN * H_DIM];
__device__ __align__(256) __nv_bfloat16 g_xl[(size_t)S_LEN * H_DIM];
__device__ __align__(256) __nv_bfloat16 g_wqh[(size_t)H_DIM * QKV_N];
__device__ __align__(256) __nv_bfloat16 g_wql[(size_t)H_DIM * QKV_N];
__device__ __align__(256) __nv_bfloat16 g_wdh[(size_t)H_DIM * H_DIM];
__device__ __align__(256) __nv_bfloat16 g_wdl[(size_t)H_DIM * H_DIM];
__device__ __align__(256) __nv_bfloat16 g_ah[(size_t)S_LEN * H_DIM];
__device__ __align__(256) __nv_bfloat16 g_al[(size_t)S_LEN * H_DIM];

/* roped operands, bf16 hi/lo */
__device__ __align__(256) __nv_bfloat16 g_qh2[(size_t)NHEAD * S_LEN * HDIM];
__device__ __align__(256) __nv_bfloat16 g_ql2[(size_t)NHEAD * S_LEN * HDIM];
__device__ __align__(256) __nv_bfloat16 g_khT[(size_t)HDIM * S_LEN];  /* [d][s] */
__device__ __align__(256) __nv_bfloat16 g_klT[(size_t)HDIM * S_LEN];
__device__ __align__(256) __nv_bfloat16 g_vh2[(size_t)S_LEN * HDIM];  /* [s][d] */
__device__ __align__(256) __nv_bfloat16 g_vl2[(size_t)S_LEN * HDIM];

/* =====================================================================
 * fp32 -> (bf16 hi, bf16 lo) split, vectorized by 4.
 * ===================================================================== */
__global__ void split4_kernel(const float* __restrict__ x,
                              __nv_bfloat16* __restrict__ hi,
                              __nv_bfloat16* __restrict__ lo,
                              int n4) {
    int i = blockIdx.x * blockDim.x + threadIdx.x;
    if (i >= n4) return;
    float4 v = ((const float4*)x)[i];
    float vv[4] = {v.x, v.y, v.z, v.w};
    __nv_bfloat16 h[4], l[4];
#pragma unroll
    for (int j = 0; j < 4; j++) {
        h[j] = __float2bfloat16(vv[j]);
        l[j] = __float2bfloat16(vv[j] - __bfloat162float(h[j]));
    }
    ((__nv_bfloat162*)hi)[2 * i + 0] = __nv_bfloat162(h[0], h[1]);
    ((__nv_bfloat162*)hi)[2 * i + 1] = __nv_bfloat162(h[2], h[3]);
    ((__nv_bfloat162*)lo)[2 * i + 0] = __nv_bfloat162(l[0], l[1]);
    ((__nv_bfloat162*)lo)[2 * i + 1] = __nv_bfloat162(l[2], l[3]);
}

/* ---- mma helpers ---- */
__device__ __forceinline__ void ldm_x4(uint32_t* r, uint32_t addr) {
    asm volatile("ldmatrix.sync.aligned.m8n8.x4.shared.b16 {%0,%1,%2,%3}, [%4];\n"
                 : "=r"(r[0]), "=r"(r[1]), "=r"(r[2]), "=r"(r[3]) : "r"(addr));
}
__device__ __forceinline__ void ldm_x4_t(uint32_t* r, uint32_t addr) {
    asm volatile("ldmatrix.sync.aligned.m8n8.x4.trans.shared.b16 {%0,%1,%2,%3}, [%4];\n"
                 : "=r"(r[0]), "=r"(r[1]), "=r"(r[2]), "=r"(r[3]) : "r"(addr));
}
__device__ __forceinline__ void mma_bf16(float* c, const uint32_t* a, const uint32_t* b) {
    asm volatile(
        "mma.sync.aligned.m16n8k16.row.col.f32.bf16.bf16.f32 "
        "{%0,%1,%2,%3}, {%4,%5,%6,%7}, {%8,%9}, {%0,%1,%2,%3};\n"
        : "+f"(c[0]), "+f"(c[1]), "+f"(c[2]), "+f"(c[3])
        : "r"(a[0]), "r"(a[1]), "r"(a[2]), "r"(a[3]), "r"(b[0]), "r"(b[1]));
}

/* FMA-only exp2 (no MUFU). x <= 0 expected; clamped below. abs err < 2e-5. */
__device__ __forceinline__ float exp2_fast(float x) {
    x = fmaxf(x, -120.0f);
    float fl = floorf(x);
    float f = x - fl;
    float p = fmaf(f, 1.540353e-4f, 1.3333558e-3f);
    p = fmaf(f, p, 9.6181291e-3f);
    p = fmaf(f, p, 5.5504109e-2f);
    p = fmaf(f, p, 2.4022651e-1f);
    p = fmaf(f, p, 6.9314718e-1f);
    p = fmaf(f, p, 1.0f);
    return __int_as_float(((int)fl + 127) << 23) * p;
}

/* =====================================================================
 * Split-bf16 GEMM (unchanged from R3): C = (Ah+Al)(Bh+Bl), 3-term.
 * ===================================================================== */
#define APAD 40
#define BPAD 72

__global__ void __launch_bounds__(256)
gemm_bf16split_kernel(const __nv_bfloat16* __restrict__ Ah,
                      const __nv_bfloat16* __restrict__ Al,
                      const __nv_bfloat16* __restrict__ Bh,
                      const __nv_bfloat16* __restrict__ Bl,
                      float* __restrict__ C,
                      int M, int N, int K) {
    __shared__ __nv_bfloat16 As[2][128][APAD];
    __shared__ __nv_bfloat16 Bs[2][32][BPAD];

    const int tid  = threadIdx.x;
    const int lane = tid & 31;
    const int wid  = tid >> 5;
    const int wm   = (wid & 3) * 32;
    const int wn   = (wid >> 2) * 32;
    const int rowBlk = blockIdx.y * 128;
    const int colBlk = blockIdx.x * 64;

    const int ar0 = tid >> 2;
    const int ac0 = (tid & 3) * 8;
    const int ar1 = (tid + 256) >> 2;
    const int ac1 = ((tid + 256) & 3) * 8;
    const int br  = tid >> 3;
    const int bc  = (tid & 7) * 8;

    const __nv_bfloat16* Ah0 = Ah + (size_t)(rowBlk + ar0) * K + ac0;
    const __nv_bfloat16* Ah1 = Ah + (size_t)(rowBlk + ar1) * K + ac1;
    const __nv_bfloat16* Al0 = Al + (size_t)(rowBlk + ar0) * K + ac0;
    const __nv_bfloat16* Al1 = Al + (size_t)(rowBlk + ar1) * K + ac1;
    const __nv_bfloat16* Bh0 = Bh + (size_t)br * N + colBlk + bc;
    const __nv_bfloat16* Bl0 = Bl + (size_t)br * N + colBlk + bc;

    uint32_t sA = (uint32_t)__cvta_generic_to_shared(&As[0][0][0]);
    uint32_t sB = (uint32_t)__cvta_generic_to_shared(&Bs[0][0][0]);

    const int lr = lane & 15;
    const int lc = (lane >> 4) << 3;

    float acc[2][4][4];
#pragma unroll
    for (int mt = 0; mt < 2; mt++)
#pragma unroll
        for (int nt = 0; nt < 4; nt++)
#pragma unroll
            for (int r = 0; r < 4; r++) acc[mt][nt][r] = 0.0f;

    const int iters = K / 32;
    uint4 pa_h0, pa_h1, pa_l0, pa_l1, pb_h, pb_l;

    pa_h0 = *(const uint4*)Ah0;  pa_h1 = *(const uint4*)Ah1;
    pa_l0 = *(const uint4*)Al0;  pa_l1 = *(const uint4*)Al1;
    pb_h  = *(const uint4*)Bh0;  pb_l  = *(const uint4*)Bl0;

    for (int it = 0; it < iters; it++) {
        *(uint4*)&As[0][ar0][ac0] = pa_h0;
        *(uint4*)&As[0][ar1][ac1] = pa_h1;
        *(uint4*)&As[1][ar0][ac0] = pa_l0;
        *(uint4*)&As[1][ar1][ac1] = pa_l1;
        *(uint4*)&Bs[0][br][bc]   = pb_h;
        *(uint4*)&Bs[1][br][bc]   = pb_l;
        __syncthreads();

        if (it + 1 < iters) {
            int ko = (it + 1) * 32;
            pa_h0 = *(const uint4*)(Ah0 + ko);  pa_h1 = *(const uint4*)(Ah1 + ko);
            pa_l0 = *(const uint4*)(Al0 + ko);  pa_l1 = *(const uint4*)(Al1 + ko);
            pb_h  = *(const uint4*)(Bh0 + (size_t)ko * N);
            pb_l  = *(const uint4*)(Bl0 + (size_t)ko * N);
        }

#pragma unroll
        for (int kk = 0; kk < 32; kk += 16) {
            uint32_t ah[2][4], al[2][4], bh[4][2], bl[4][2];
#pragma unroll
            for (int mt = 0; mt < 2; mt++) {
                uint32_t arow = (uint32_t)(wm + mt * 16 + lr);
                uint32_t acol = (uint32_t)(kk + lc);
                ldm_x4(ah[mt], sA + (arow * APAD + acol) * 2);
                ldm_x4(al[mt], sA + ((128 + arow) * APAD + acol) * 2);
            }
#pragma unroll
            for (int half = 0; half < 2; half++) {
                uint32_t brow = (uint32_t)(kk + lr);
                uint32_t bcol = (uint32_t)(wn + half * 16 + lc);
                uint32_t r[4];
                ldm_x4_t(r, sB + (brow * BPAD + bcol) * 2);
                bh[half * 2 + 0][0] = r[0]; bh[half * 2 + 0][1] = r[1];
                bh[half * 2 + 1][0] = r[2]; bh[half * 2 + 1][1] = r[3];
                ldm_x4_t(r, sB + ((32 + brow) * BPAD + bcol) * 2);
                bl[half * 2 + 0][0] = r[0]; bl[half * 2 + 0][1] = r[1];
                bl[half * 2 + 1][0] = r[2]; bl[half * 2 + 1][1] = r[3];
            }
#pragma unroll
            for (int mt = 0; mt < 2; mt++)
#pragma unroll
                for (int nt = 0; nt < 4; nt++) {
                    mma_bf16(acc[mt][nt], ah[mt], bh[nt]);
                    mma_bf16(acc[mt][nt], ah[mt], bl[nt]);
                    mma_bf16(acc[mt][nt], al[mt], bh[nt]);
                }
        }
        __syncthreads();
    }

#pragma unroll
    for (int mt = 0; mt < 2; mt++) {
        int row = rowBlk + wm + mt * 16 + (lane >> 2);
#pragma unroll
        for (int nt = 0; nt < 4; nt++) {
            int col = colBlk + wn + nt * 8 + (lane & 3) * 2;
            *(float2*)&C[(size_t)row * N + col] =
                make_float2(acc[mt][nt][0], acc[mt][nt][1]);
            *(float2*)&C[(size_t)(row + 8) * N + col] =
                make_float2(acc[mt][nt][2], acc[mt][nt][3]);
        }
    }
}

/* =====================================================================
 * RoPE + split to bf16 hi/lo. sincos computed once per row (32 freqs).
 * Q -> head-major [h][s][d]; K -> transposed [d][s]; V -> [s][d].
 * ===================================================================== */
__global__ void rope_split_bf16_kernel(const float* __restrict__ qkv,
                                       __nv_bfloat16* __restrict__ qh,
                                       __nv_bfloat16* __restrict__ ql,
                                       __nv_bfloat16* __restrict__ khT,
                                       __nv_bfloat16* __restrict__ klT,
                                       __nv_bfloat16* __restrict__ vh,
                                       __nv_bfloat16* __restrict__ vl) {
    __shared__ float cs_s[32], sn_s[32];
    const int s = blockIdx.x;
    const float* row = qkv + (size_t)s * QKV_N;

    if (threadIdx.x < 32) {
        const float L2C = 13.28771237954945f / 32.0f;   /* log2(10000)/32 */
        float inv = exp2f(-(float)threadIdx.x * L2C);
        float sn, cs;
        sincosf((float)s * inv, &sn, &cs);
        cs_s[threadIdx.x] = cs;
        sn_s[threadIdx.x] = sn;
    }
    __syncthreads();

    for (int col = threadIdx.x; col < QKV_N; col += blockDim.x) {
        const int h = col >> 6;
        const int d = col & 63;
        float val = row[col];
        float o;
        if (h < NHEAD + 1) {
            const int jj = d & 31;
            float other = (d < 32) ? -row[h * 64 + d + 32] : row[h * 64 + d - 32];
            o = val * cs_s[jj] + other * sn_s[jj];
        } else {
            o = val;
        }
        __nv_bfloat16 hi = __float2bfloat16(o);
        __nv_bfloat16 lo = __float2bfloat16(o - __bfloat162float(hi));
        if (h < NHEAD) {
            size_t idx = ((size_t)h * S_LEN + s) * HDIM + d;
            qh[idx] = hi; ql[idx] = lo;
        } else if (h == NHEAD) {
            size_t idx = (size_t)d * S_LEN + s;
            khT[idx] = hi; klT[idx] = lo;
        } else {
            size_t idx = (size_t)s * HDIM + d;
            vh[idx] = hi; vl[idx] = lo;
        }
    }
}

/* =====================================================================
 * Tensor-core flash attention (split-bf16, FMA exp2).
 * Block = (64 q-rows, head). 4 warps; warp w owns rows [16w,16w+16).
 * P kept in registers (mma C layout == mma A layout). Writes bf16 hi/lo
 * output directly for the dense GEMM.
 * ===================================================================== */
#define AT_PITCH 72
#define AT_TILE  (64 * AT_PITCH)      /* 4608 bf16 per tile */
#define OFF_QH 0
#define OFF_QL (1 * AT_TILE)
#define OFF_KH (2 * AT_TILE)
#define OFF_KL (3 * AT_TILE)
#define OFF_VH (4 * AT_TILE)
#define OFF_VL (5 * AT_TILE)
#define AT_SMEM_BYTES (6 * AT_TILE * 2)   /* 55296 */

__global__ void __launch_bounds__(128)
attn_mma_kernel(const __nv_bfloat16* __restrict__ Qh,
                const __nv_bfloat16* __restrict__ Ql,
                const __nv_bfloat16* __restrict__ KhT,
                const __nv_bfloat16* __restrict__ KlT,
                const __nv_bfloat16* __restrict__ Vh,
                const __nv_bfloat16* __restrict__ Vl,
                __nv_bfloat16* __restrict__ Oh,
                __nv_bfloat16* __restrict__ Ol) {
    extern __shared__ unsigned char sraw[];
    __nv_bfloat16* S = (__nv_bfloat16*)sraw;
    uint32_t sbase = (uint32_t)__cvta_generic_to_shared(S);

    const int tid  = threadIdx.x;
    const int lane = tid & 31;
    const int w    = tid >> 5;
    const int qt   = blockIdx.x;
    const int h    = blockIdx.y;
    const int qs0  = qt * 64;

    const int lr = lane & 15;
    const int lc = (lane >> 4) << 3;
    const int qr = lane >> 2;          /* quad row 0..7 */
    const int qc = (lane & 3) * 2;     /* quad col pair base */

    /* load Q hi/lo tiles (64x64 each) */
    {
        const __nv_bfloat16* qhg = Qh + ((size_t)h * S_LEN + qs0) * HDIM;
        const __nv_bfloat16* qlg = Ql + ((size_t)h * S_LEN + qs0) * HDIM;
        for (int i = tid; i < 512; i += 128) {
            int r = i >> 3, c = (i & 7) * 8;
            *(uint4*)&S[OFF_QH + r * AT_PITCH + c] = *(const uint4*)&qhg[r * 64 + c];
            *(uint4*)&S[OFF_QL + r * AT_PITCH + c] = *(const uint4*)&qlg[r * 64 + c];
        }
    }

    float m1 = -1e30f, m2 = -1e30f, l1 = 0.0f, l2 = 0.0f;
    float o[8][4];
#pragma unroll
    for (int nt = 0; nt < 8; nt++)
#pragma unroll
        for (int j = 0; j < 4; j++) o[nt][j] = 0.0f;

    const float SC = 0.125f * 1.4426950408889634f;   /* scale * log2(e) */
    const int row1 = w * 16 + qr;
    const int row2 = row1 + 8;

    for (int jt = 0; jt <= qt; jt++) {
        /* load K (transposed [d][s]) and V ([s][d]) hi/lo tiles */
        for (int i = tid; i < 512; i += 128) {
            int r = i >> 3, c = (i & 7) * 8;
            *(uint4*)&S[OFF_KH + r * AT_PITCH + c] =
                *(const uint4*)&KhT[(size_t)r * S_LEN + jt * 64 + c];
            *(uint4*)&S[OFF_KL + r * AT_PITCH + c] =
                *(const uint4*)&KlT[(size_t)r * S_LEN + jt * 64 + c];
            *(uint4*)&S[OFF_VH + r * AT_PITCH + c] =
                *(const uint4*)&Vh[(size_t)(jt * 64 + r) * 64 + c];
            *(uint4*)&S[OFF_VL + r * AT_PITCH + c] =
                *(const uint4*)&Vl[(size_t)(jt * 64 + r) * 64 + c];
        }
        __syncthreads();

        /* ---- S = Q K^T (3-term split) ---- */
        float s[8][4];
#pragma unroll
        for (int nt = 0; nt < 8; nt++)
#pragma unroll
            for (int j = 0; j < 4; j++) s[nt][j] = 0.0f;

#pragma unroll
        for (int kk = 0; kk < 64; kk += 16) {
            uint32_t qfh[4], qfl[4];
            ldm_x4(qfh, sbase + (uint32_t)(OFF_QH + (w * 16 + lr) * AT_PITCH + kk + lc) * 2);
            ldm_x4(qfl, sbase + (uint32_t)(OFF_QL + (w * 16 + lr) * AT_PITCH + kk + lc) * 2);
#pragma unroll
            for (int half = 0; half < 4; half++) {
                uint32_t bh[2][2], bl[2][2], r4[4];
                ldm_x4_t(r4, sbase + (uint32_t)(OFF_KH + (kk + lr) * AT_PITCH + half * 16 + lc) * 2);
                bh[0][0] = r4[0]; bh[0][1] = r4[1]; bh[1][0] = r4[2]; bh[1][1] = r4[3];
                ldm_x4_t(r4, sbase + (uint32_t)(OFF_KL + (kk + lr) * AT_PITCH + half * 16 + lc) * 2);
                bl[0][0] = r4[0]; bl[0][1] = r4[1]; bl[1][0] = r4[2]; bl[1][1] = r4[3];
#pragma unroll
                for (int t = 0; t < 2; t++) {
                    int nt = half * 2 + t;
                    mma_bf16(s[nt], qfh, bh[t]);
                    mma_bf16(s[nt], qfh, bl[t]);
                    mma_bf16(s[nt], qfl, bh[t]);
                }
            }
        }

        /* scale into log2 domain + causal mask */
#pragma unroll
        for (int nt = 0; nt < 8; nt++)
#pragma unroll
            for (int j = 0; j < 4; j++) s[nt][j] *= SC;

        if (jt == qt) {
#pragma unroll
            for (int nt = 0; nt < 8; nt++) {
                int c0 = nt * 8 + qc;
                if (c0     > row1) s[nt][0] = -1e30f;
                if (c0 + 1 > row1) s[nt][1] = -1e30f;
                if (c0     > row2) s[nt][2] = -1e30f;
                if (c0 + 1 > row2) s[nt][3] = -1e30f;
            }
        }

        /* ---- online softmax (per-warp; rows r1, r2 per thread) ---- */
        float pm1 = -1e30f, pm2 = -1e30f;
#pragma unroll
        for (int nt = 0; nt < 8; nt++) {
            pm1 = fmaxf(pm1, fmaxf(s[nt][0], s[nt][1]));
            pm2 = fmaxf(pm2, fmaxf(s[nt][2], s[nt][3]));
        }
        pm1 = fmaxf(pm1, __shfl_xor_sync(0xffffffff, pm1, 1));
        pm1 = fmaxf(pm1, __shfl_xor_sync(0xffffffff, pm1, 2));
        pm2 = fmaxf(pm2, __shfl_xor_sync(0xffffffff, pm2, 1));
        pm2 = fmaxf(pm2, __shfl_xor_sync(0xffffffff, pm2, 2));

        float mn1 = fmaxf(m1, pm1), mn2 = fmaxf(m2, pm2);
        float rs1 = exp2_fast(m1 - mn1), rs2 = exp2_fast(m2 - mn2);
        m1 = mn1; m2 = mn2;

        float sum1 = 0.0f, sum2 = 0.0f;
        uint32_t phA[8], phB[8], plA[8], plB[8];
#pragma unroll
        for (int nt = 0; nt < 8; nt++) {
            float e0 = exp2_fast(s[nt][0] - m1);
            float e1 = exp2_fast(s[nt][1] - m1);
            float e2 = exp2_fast(s[nt][2] - m2);
            float e3 = exp2_fast(s[nt][3] - m2);
            sum1 += e0 + e1;
            sum2 += e2 + e3;
            __nv_bfloat162 h01 = __floats2bfloat162_rn(e0, e1);
            __nv_bfloat162 h23 = __floats2bfloat162_rn(e2, e3);
            float r0 = e0 - __bfloat162float(h01.x);
            float r1 = e1 - __bfloat162float(h01.y);
            float r2 = e2 - __bfloat162float(h23.x);
            float r3 = e3 - __bfloat162float(h23.y);
            __nv_bfloat162 l01 = __floats2bfloat162_rn(r0, r1);
            __nv_bfloat162 l23 = __floats2bfloat162_rn(r2, r3);
            phA[nt] = *(uint32_t*)&h01;  phB[nt] = *(uint32_t*)&h23;
            plA[nt] = *(uint32_t*)&l01;  plB[nt] = *(uint32_t*)&l23;
        }
        sum1 += __shfl_xor_sync(0xffffffff, sum1, 1);
        sum1 += __shfl_xor_sync(0xffffffff, sum1, 2);
        sum2 += __shfl_xor_sync(0xffffffff, sum2, 1);
        sum2 += __shfl_xor_sync(0xffffffff, sum2, 2);
        l1 = l1 * rs1 + sum1;
        l2 = l2 * rs2 + sum2;

#pragma unroll
        for (int nt = 0; nt < 8; nt++) {
            o[nt][0] *= rs1; o[nt][1] *= rs1;
            o[nt][2] *= rs2; o[nt][3] *= rs2;
        }

        /* ---- O += P V (3-term split; P in regs as A operand) ---- */
#pragma unroll
        for (int t = 0; t < 4; t++) {
            uint32_t aH[4] = {phA[2 * t], phB[2 * t], phA[2 * t + 1], phB[2 * t + 1]};
            uint32_t aL[4] = {plA[2 * t], plB[2 * t], plA[2 * t + 1], plB[2 * t + 1]};
#pragma unroll
            for (int half = 0; half < 4; half++) {
                uint32_t bh[2][2], bl[2][2], r4[4];
                ldm_x4_t(r4, sbase + (uint32_t)(OFF_VH + (t * 16 + lr) * AT_PITCH + half * 16 + lc) * 2);
                bh[0][0] = r4[0]; bh[0][1] = r4[1]; bh[1][0] = r4[2]; bh[1][1] = r4[3];
                ldm_x4_t(r4, sbase + (uint32_t)(OFF_VL + (t * 16 + lr) * AT_PITCH + half * 16 + lc) * 2);
                bl[0][0] = r4[0]; bl[0][1] = r4[1]; bl[1][0] = r4[2]; bl[1][1] = r4[3];
#pragma unroll
                for (int tt = 0; tt < 2; tt++) {
                    int nt = half * 2 + tt;
                    mma_bf16(o[nt], aH, bh[tt]);
                    mma_bf16(o[nt], aL, bh[tt]);
                    mma_bf16(o[nt], aH, bl[tt]);
                }
            }
        }
        __syncthreads();
    }

    /* ---- epilogue: normalize, split bf16 hi/lo, write ---- */
    float inv1 = 1.0f / l1, inv2 = 1.0f / l2;
    int gr1 = qs0 + row1, gr2 = qs0 + row2;
#pragma unroll
    for (int nt = 0; nt < 8; nt++) {
        int col = h * 64 + nt * 8 + qc;
        float v0 = o[nt][0] * inv1, v1 = o[nt][1] * inv1;
        float v2 = o[nt][2] * inv2, v3 = o[nt][3] * inv2;
        __nv_bfloat162 h01 = __floats2bfloat162_rn(v0, v1);
        __nv_bfloat162 h23 = __floats2bfloat162_rn(v2, v3);
        __nv_bfloat162 l01 = __floats2bfloat162_rn(v0 - __bfloat162float(h01.x),
                                                   v1 - __bfloat162float(h01.y));
        __nv_bfloat162 l23 = __floats2bfloat162_rn(v2 - __bfloat162float(h23.x),
                                                   v3 - __bfloat162float(h23.y));
        *(uint32_t*)&Oh[(size_t)gr1 * H_DIM + col] = *(uint32_t*)&h01;
        *(uint32_t*)&Ol[(size_t)gr1 * H_DIM + col] = *(uint32_t*)&l01;
        *(uint32_t*)&Oh[(size_t)gr2 * H_DIM + col] = *(uint32_t*)&h23;
        *(uint32_t*)&Ol[(size_t)gr2 * H_DIM + col] = *(uint32_t*)&l23;
    }
}

/* ===================================================================== */
extern "C" void kernel_launch(void* const* d_in, const int* in_sizes, int n_in,
                              void* d_out, int out_size) {
    const float* hidden  = (const float*)d_in[0];
    const float* qkv_w   = (const float*)d_in[2];
    const float* dense_w = (const float*)d_in[3];
    float* out = (float*)d_out;

    float* qkv_p;
    cudaGetSymbolAddress((void**)&qkv_p, g_qkv);

    __nv_bfloat16 *xh, *xl, *wqh, *wql, *wdh, *wdl, *ah, *al;
    __nv_bfloat16 *qh2, *ql2, *khT, *klT, *vh2, *vl2;
    cudaGetSymbolAddress((void**)&xh,  g_xh);
    cudaGetSymbolAddress((void**)&xl,  g_xl);
    cudaGetSymbolAddress((void**)&wqh, g_wqh);
    cudaGetSymbolAddress((void**)&wql, g_wql);
    cudaGetSymbolAddress((void**)&wdh, g_wdh);
    cudaGetSymbolAddress((void**)&wdl, g_wdl);
    cudaGetSymbolAddress((void**)&ah,  g_ah);
    cudaGetSymbolAddress((void**)&al,  g_al);
    cudaGetSymbolAddress((void**)&qh2, g_qh2);
    cudaGetSymbolAddress((void**)&ql2, g_ql2);
    cudaGetSymbolAddress((void**)&khT, g_khT);
    cudaGetSymbolAddress((void**)&klT, g_klT);
    cudaGetSymbolAddress((void**)&vh2, g_vh2);
    cudaGetSymbolAddress((void**)&vl2, g_vl2);

    cudaFuncSetAttribute(attn_mma_kernel, cudaFuncAttributeMaxDynamicSharedMemorySize,
                         AT_SMEM_BYTES);

    /* 0) split inputs/weights to bf16 hi/lo */
    {
        int n4;
        n4 = (S_LEN * H_DIM) / 4;
        split4_kernel<<<(n4 + 255) / 256, 256>>>(hidden, xh, xl, n4);
        n4 = (H_DIM * QKV_N) / 4;
        split4_kernel<<<(n4 + 255) / 256, 256>>>(qkv_w, wqh, wql, n4);
        n4 = (H_DIM * H_DIM) / 4;
        split4_kernel<<<(n4 + 255) / 256, 256>>>(dense_w, wdh, wdl, n4);
    }

    /* 1) qkv = x @ qkv_w (tensor cores) */
    gemm_bf16split_kernel<<<dim3(QKV_N / 64, S_LEN / 128), 256>>>(
        xh, xl, wqh, wql, qkv_p, S_LEN, QKV_N, H_DIM);

    /* 2) RoPE + bf16 hi/lo split (Q head-major, K transposed, V natural) */
    rope_split_bf16_kernel<<<S_LEN, 256>>>(qkv_p, qh2, ql2, khT, klT, vh2, vl2);

    /* 3) tensor-core causal flash attention -> bf16 hi/lo attn */
    attn_mma_kernel<<<dim3(S_LEN / 64, NHEAD), 128, AT_SMEM_BYTES>>>(
        qh2, ql2, khT, klT, vh2, vl2, ah, al);

    /* 4) out = attn @ dense_w (tensor cores) */
    gemm_bf16split_kernel<<<dim3(H_DIM / 64, S_LEN / 128), 256>>>(
        ah, al, wdh, wdl, out, S_LEN, H_DIM, H_DIM);
}